// round 9
// baseline (speedup 1.0000x reference)
#include <cuda_runtime.h>
#include <math.h>

#define Bn   32
#define Nn   1024
#define FIN  512
#define H1n  256
#define H2n  128

typedef unsigned long long ull;

// ---- scratch (device globals; no allocation allowed) ----
__device__ float g_h1[Bn * Nn * H1n];   // 32 MB
__device__ float g_g1[Bn * Nn * H1n];   // 32 MB
__device__ float g_h2[Bn * Nn * H2n];   // 16 MB
__device__ float g_el[Bn * Nn];
__device__ float g_er[Bn * Nn];
__device__ float g_sb[Bn * 2];          // per-batch (scale, bias)
__device__ float g_v[Bn * Nn];          // g2 @ Wg

// packed dual-fp32 FMA: d.lo += a.lo*b.lo ; d.hi += a.hi*b.hi
__device__ __forceinline__ void ffma2(ull& d, ull a, ull b) {
    asm("fma.rn.f32x2 %0, %1, %2, %0;" : "+l"(d) : "l"(a), "l"(b));
}
__device__ __forceinline__ float pair_sum(ull v) {
    union { ull u; float2 f; } c; c.u = v;
    return c.f.x + c.f.y;
}

// ============================================================
// fp32 GEMM: C[M,N] = A[M,K] * B[K,N]   (unchanged from R5)
// BM=128, BN=128, BK=8, 256 threads, 8x8 per thread
// ============================================================
__global__ __launch_bounds__(256) void gemm_kernel(
    const float* __restrict__ A, const float* __restrict__ B,
    float* __restrict__ C, int M, int N, int K)
{
    __shared__ float As[8][132];
    __shared__ float Bs[8][128];
    int t = threadIdx.x;
    int bm = blockIdx.y * 128, bn = blockIdx.x * 128;
    int tx = t & 15, ty = t >> 4;
    int trow = ty * 8;
    int tc0 = tx * 4;

    float acc[8][8];
#pragma unroll
    for (int i = 0; i < 8; i++)
#pragma unroll
        for (int j = 0; j < 8; j++) acc[i][j] = 0.f;

    int arow = t >> 1, ak = (t & 1) * 4;
    int bk = t >> 5, bcol = (t & 31) * 4;

    for (int k0 = 0; k0 < K; k0 += 8) {
        float4 av = *(const float4*)&A[(size_t)(bm + arow) * K + k0 + ak];
        As[ak + 0][arow] = av.x; As[ak + 1][arow] = av.y;
        As[ak + 2][arow] = av.z; As[ak + 3][arow] = av.w;
        *(float4*)&Bs[bk][bcol] = *(const float4*)&B[(size_t)(k0 + bk) * N + bn + bcol];
        __syncthreads();
#pragma unroll
        for (int kk = 0; kk < 8; kk++) {
            float4 a0 = *(const float4*)&As[kk][trow];
            float4 a1 = *(const float4*)&As[kk][trow + 4];
            float4 b0 = *(const float4*)&Bs[kk][tc0];
            float4 b1 = *(const float4*)&Bs[kk][tc0 + 64];
            float ar[8] = {a0.x, a0.y, a0.z, a0.w, a1.x, a1.y, a1.z, a1.w};
#pragma unroll
            for (int ii = 0; ii < 8; ii++) {
                acc[ii][0] += ar[ii] * b0.x;
                acc[ii][1] += ar[ii] * b0.y;
                acc[ii][2] += ar[ii] * b0.z;
                acc[ii][3] += ar[ii] * b0.w;
                acc[ii][4] += ar[ii] * b1.x;
                acc[ii][5] += ar[ii] * b1.y;
                acc[ii][6] += ar[ii] * b1.z;
                acc[ii][7] += ar[ii] * b1.w;
            }
        }
        __syncthreads();
    }
#pragma unroll
    for (int ii = 0; ii < 8; ii++) {
        float* cr = &C[(size_t)(bm + trow + ii) * N + bn];
        *(float4*)&cr[tc0]      = make_float4(acc[ii][0], acc[ii][1], acc[ii][2], acc[ii][3]);
        *(float4*)&cr[tc0 + 64] = make_float4(acc[ii][4], acc[ii][5], acc[ii][6], acc[ii][7]);
    }
}

// ============================================================
// el/er: per row dot with a[0:Fo] and a[Fo:2Fo]. One warp/row.
// ============================================================
__global__ __launch_bounds__(256) void eler_kernel(
    const float* __restrict__ h, const float* __restrict__ a,
    float* __restrict__ el, float* __restrict__ er, int Fo)
{
    int row = (blockIdx.x * blockDim.x + threadIdx.x) >> 5;
    int lane = threadIdx.x & 31;
    if (row >= Bn * Nn) return;
    const float* hr = h + (size_t)row * Fo;
    float sl = 0.f, sr = 0.f;
    for (int f = lane; f < Fo; f += 32) {
        float hv = hr[f];
        sl += hv * a[f];
        sr += hv * a[Fo + f];
    }
#pragma unroll
    for (int o = 16; o; o >>= 1) {
        sl += __shfl_xor_sync(0xffffffffu, sl, o);
        sr += __shfl_xor_sync(0xffffffffu, sr, o);
    }
    if (lane == 0) { el[row] = sl; er[row] = sr; }
}

// ============================================================
// per-batch min/max of el, er -> (scale, bias)
// ============================================================
__global__ __launch_bounds__(256) void minmax_kernel(
    const float* __restrict__ el, const float* __restrict__ er,
    float* __restrict__ sb)
{
    int b = blockIdx.x, t = threadIdx.x;
    const float* e1 = el + b * Nn;
    const float* e2 = er + b * Nn;
    float mnl = 1e30f, mxl = -1e30f, mnr = 1e30f, mxr = -1e30f;
    for (int i = t; i < Nn; i += 256) {
        float a = e1[i]; mnl = fminf(mnl, a); mxl = fmaxf(mxl, a);
        float c = e2[i]; mnr = fminf(mnr, c); mxr = fmaxf(mxr, c);
    }
#pragma unroll
    for (int o = 16; o; o >>= 1) {
        mnl = fminf(mnl, __shfl_xor_sync(0xffffffffu, mnl, o));
        mxl = fmaxf(mxl, __shfl_xor_sync(0xffffffffu, mxl, o));
        mnr = fminf(mnr, __shfl_xor_sync(0xffffffffu, mnr, o));
        mxr = fmaxf(mxr, __shfl_xor_sync(0xffffffffu, mxr, o));
    }
    __shared__ float s[8][4];
    int w = t >> 5, lane = t & 31;
    if (lane == 0) { s[w][0] = mnl; s[w][1] = mxl; s[w][2] = mnr; s[w][3] = mxr; }
    __syncthreads();
    if (t == 0) {
#pragma unroll
        for (int i = 1; i < 8; i++) {
            mnl = fminf(mnl, s[i][0]); mxl = fmaxf(mxl, s[i][1]);
            mnr = fminf(mnr, s[i][2]); mxr = fmaxf(mxr, s[i][3]);
        }
        float emin = mnl + mnr; emin = emin >= 0.f ? emin : 0.01f * emin;
        float emax = mxl + mxr; emax = emax >= 0.f ? emax : 0.01f * emax;
        float sc = 30.f / (emax - emin);
        sb[b * 2] = sc;
        sb[b * 2 + 1] = -emin * sc - 20.f;
    }
}

// ============================================================
// Fused layer-1 attention GEMM, FFMA2 version.
// Block tile: 64 i x 128 f.  256 threads, 8i x 4f per thread,
// accumulators packed over j-parity (even j in .lo, odd j in .hi).
// Shared tiles stored pair-interleaved:
//   hs2f[jp][f*2+p]   = h[2*jp+p][f]
//   at2f[i][jp*2+p]   = att[i][2*jp+p]
// ============================================================
__global__ __launch_bounds__(256) void fused_att1_kernel(
    const float* __restrict__ h, const float* __restrict__ el,
    const float* __restrict__ er, const float* __restrict__ sb,
    float* __restrict__ out)
{
    __shared__ float hs2f[16][258];   // 16 jp x (128 f pairs), 16.5 KB
    __shared__ float at2f[64][34];    // 64 i  x (16 jp pairs),  8.7 KB
    int b = blockIdx.z;
    int i0 = blockIdx.x * 64;
    int f0 = blockIdx.y * 128;
    int t = threadIdx.x;
    float scale = sb[b * 2], bias = sb[b * 2 + 1];
    int fc0 = (t & 31) * 4;          // 4 consecutive f columns
    int ir0 = (t >> 5) * 8;          // warp-uniform i base -> LDS broadcast

    ull acc[8][4];
#pragma unroll
    for (int i = 0; i < 8; i++)
#pragma unroll
        for (int q = 0; q < 4; q++) acc[i][q] = 0ull;

    const float* hb = h + (size_t)b * Nn * H1n;
    const float* elb = el + b * Nn;
    const float* erb = er + b * Nn;
    int arow = t >> 2;               // sigmoid row 0..63
    int jpb = (t & 3) * 4;           // 4 jp pairs (8 j) per thread
    float eli = elb[i0 + arow];

    for (int j0 = 0; j0 < Nn; j0 += 32) {
        // load h tile 32 x 128 -> pair-interleaved
#pragma unroll
        for (int r = 0; r < 4; r++) {
            int idx = t + r * 256;
            int jj = idx >> 5, fq = (idx & 31) * 4;
            float4 v = *(const float4*)&hb[(size_t)(j0 + jj) * H1n + f0 + fq];
            int jp = jj >> 1, p = jj & 1;
            hs2f[jp][(fq + 0) * 2 + p] = v.x;
            hs2f[jp][(fq + 1) * 2 + p] = v.y;
            hs2f[jp][(fq + 2) * 2 + p] = v.z;
            hs2f[jp][(fq + 3) * 2 + p] = v.w;
        }
        // attention pairs
#pragma unroll
        for (int r = 0; r < 4; r++) {
            int j = j0 + (jpb + r) * 2;
            float x0 = eli + erb[j];
            x0 = x0 >= 0.f ? x0 : 0.01f * x0;
            x0 = scale * x0 + bias;
            float x1 = eli + erb[j + 1];
            x1 = x1 >= 0.f ? x1 : 0.01f * x1;
            x1 = scale * x1 + bias;
            *(float2*)&at2f[arow][(jpb + r) * 2] =
                make_float2(1.f / (1.f + __expf(-x0)), 1.f / (1.f + __expf(-x1)));
        }
        __syncthreads();
#pragma unroll
        for (int jp = 0; jp < 16; jp++) {
            ull hp0 = *(const ull*)&hs2f[jp][(fc0 + 0) * 2];
            ull hp1 = *(const ull*)&hs2f[jp][(fc0 + 1) * 2];
            ull hp2 = *(const ull*)&hs2f[jp][(fc0 + 2) * 2];
            ull hp3 = *(const ull*)&hs2f[jp][(fc0 + 3) * 2];
#pragma unroll
            for (int ii = 0; ii < 8; ii++) {
                ull ap = *(const ull*)&at2f[ir0 + ii][jp * 2];
                ffma2(acc[ii][0], ap, hp0);
                ffma2(acc[ii][1], ap, hp1);
                ffma2(acc[ii][2], ap, hp2);
                ffma2(acc[ii][3], ap, hp3);
            }
        }
        __syncthreads();
    }
    float* ob = out + (size_t)b * Nn * H1n;
#pragma unroll
    for (int ii = 0; ii < 8; ii++) {
        float s0 = pair_sum(acc[ii][0]);
        float s1 = pair_sum(acc[ii][1]);
        float s2 = pair_sum(acc[ii][2]);
        float s3 = pair_sum(acc[ii][3]);
        float4 v;
        v.x = s0 > 0.f ? s0 : __expf(s0) - 1.f;
        v.y = s1 > 0.f ? s1 : __expf(s1) - 1.f;
        v.z = s2 > 0.f ? s2 : __expf(s2) - 1.f;
        v.w = s3 > 0.f ? s3 : __expf(s3) - 1.f;
        *(float4*)&ob[(size_t)(i0 + ir0 + ii) * H1n + f0 + fc0] = v;
    }
}

// ============================================================
// Fused layer-2 attention GEMM, FFMA2 version. Also writes fc2.
// Block tile: 64 i x 128 f (full H2). 256 threads, 8i x 4f.
// ============================================================
__global__ __launch_bounds__(256) void fused_att2_kernel(
    const float* __restrict__ h, const float* __restrict__ el,
    const float* __restrict__ er, const float* __restrict__ sb,
    float* __restrict__ fc2, float* __restrict__ g2)
{
    __shared__ float hs2f[16][258];
    __shared__ float at2f[64][34];
    int b = blockIdx.y;
    int i0 = blockIdx.x * 64;
    int t = threadIdx.x;
    float scale = sb[b * 2], bias = sb[b * 2 + 1];
    int fc0 = (t & 31) * 4;
    int ir0 = (t >> 5) * 8;

    ull acc[8][4];
#pragma unroll
    for (int i = 0; i < 8; i++)
#pragma unroll
        for (int q = 0; q < 4; q++) acc[i][q] = 0ull;

    const float* hb = h + (size_t)b * Nn * H2n;
    const float* elb = el + b * Nn;
    const float* erb = er + b * Nn;
    int arow = t >> 2;
    int jpb = (t & 3) * 4;
    float eli = elb[i0 + arow];

    for (int j0 = 0; j0 < Nn; j0 += 32) {
#pragma unroll
        for (int r = 0; r < 4; r++) {
            int idx = t + r * 256;
            int jj = idx >> 5, fq = (idx & 31) * 4;
            float4 v = *(const float4*)&hb[(size_t)(j0 + jj) * H2n + fq];
            int jp = jj >> 1, p = jj & 1;
            hs2f[jp][(fq + 0) * 2 + p] = v.x;
            hs2f[jp][(fq + 1) * 2 + p] = v.y;
            hs2f[jp][(fq + 2) * 2 + p] = v.z;
            hs2f[jp][(fq + 3) * 2 + p] = v.w;
        }
        float av[8];
#pragma unroll
        for (int r = 0; r < 4; r++) {
            int j = j0 + (jpb + r) * 2;
            float x0 = eli + erb[j];
            x0 = x0 >= 0.f ? x0 : 0.01f * x0;
            x0 = scale * x0 + bias;
            float x1 = eli + erb[j + 1];
            x1 = x1 >= 0.f ? x1 : 0.01f * x1;
            x1 = scale * x1 + bias;
            float s0 = 1.f / (1.f + __expf(-x0));
            float s1 = 1.f / (1.f + __expf(-x1));
            av[r * 2] = s0; av[r * 2 + 1] = s1;
            *(float2*)&at2f[arow][(jpb + r) * 2] = make_float2(s0, s1);
        }
        // write att tile (= fc2 output), coalesced
        float* fr = fc2 + (size_t)(b * Nn + i0 + arow) * Nn + j0 + jpb * 2;
        *(float4*)&fr[0] = make_float4(av[0], av[1], av[2], av[3]);
        *(float4*)&fr[4] = make_float4(av[4], av[5], av[6], av[7]);
        __syncthreads();
#pragma unroll
        for (int jp = 0; jp < 16; jp++) {
            ull hp0 = *(const ull*)&hs2f[jp][(fc0 + 0) * 2];
            ull hp1 = *(const ull*)&hs2f[jp][(fc0 + 1) * 2];
            ull hp2 = *(const ull*)&hs2f[jp][(fc0 + 2) * 2];
            ull hp3 = *(const ull*)&hs2f[jp][(fc0 + 3) * 2];
#pragma unroll
            for (int ii = 0; ii < 8; ii++) {
                ull ap = *(const ull*)&at2f[ir0 + ii][jp * 2];
                ffma2(acc[ii][0], ap, hp0);
                ffma2(acc[ii][1], ap, hp1);
                ffma2(acc[ii][2], ap, hp2);
                ffma2(acc[ii][3], ap, hp3);
            }
        }
        __syncthreads();
    }
    float* ob = g2 + (size_t)b * Nn * H2n;
#pragma unroll
    for (int ii = 0; ii < 8; ii++) {
        *(float4*)&ob[(size_t)(i0 + ir0 + ii) * H2n + fc0] =
            make_float4(pair_sum(acc[ii][0]), pair_sum(acc[ii][1]),
                        pair_sum(acc[ii][2]), pair_sum(acc[ii][3]));
    }
}

// ============================================================
// v[b,j] = g2[b,j,:] . Wg  (one warp per row)
// ============================================================
__global__ __launch_bounds__(256) void v_kernel(
    const float* __restrict__ g2, const float* __restrict__ Wg,
    float* __restrict__ v)
{
    int row = (blockIdx.x * blockDim.x + threadIdx.x) >> 5;
    int lane = threadIdx.x & 31;
    if (row >= Bn * Nn) return;
    const float* g = g2 + (size_t)row * H2n;
    float s = 0.f;
#pragma unroll
    for (int f = lane; f < H2n; f += 32) s += g[f] * Wg[f];
#pragma unroll
    for (int o = 16; o; o >>= 1) s += __shfl_xor_sync(0xffffffffu, s, o);
    if (lane == 0) v[row] = s;
}

// ============================================================
// out[b,i] = leaky( sum_j fc2[b,i,j]*v[b,j] + bg, 0.01 )
// ============================================================
__global__ __launch_bounds__(256) void z_kernel(
    const float* __restrict__ fc2, const float* __restrict__ v,
    const float* __restrict__ bg, float* __restrict__ out)
{
    int row = blockIdx.x;
    int b = row >> 10;
    int t = threadIdx.x;
    const float* fr = fc2 + (size_t)row * Nn;
    const float* vb = v + b * Nn;
    float4 f4 = *(const float4*)&fr[t * 4];
    float4 v4 = *(const float4*)&vb[t * 4];
    float s = f4.x * v4.x + f4.y * v4.y + f4.z * v4.z + f4.w * v4.w;
#pragma unroll
    for (int o = 16; o; o >>= 1) s += __shfl_xor_sync(0xffffffffu, s, o);
    __shared__ float red[8];
    int w = t >> 5, lane = t & 31;
    if (lane == 0) red[w] = s;
    __syncthreads();
    if (t == 0) {
        float z = red[0] + red[1] + red[2] + red[3]
                + red[4] + red[5] + red[6] + red[7] + bg[0];
        out[row] = z >= 0.f ? z : 0.01f * z;
    }
}

// ============================================================
extern "C" void kernel_launch(void* const* d_in, const int* in_sizes, int n_in,
                              void* d_out, int out_size)
{
    const float* x  = (const float*)d_in[0];
    // d_in[1] = edge_weight (unused by reference)
    const float* W1 = (const float*)d_in[2];
    const float* a1 = (const float*)d_in[3];
    const float* W2 = (const float*)d_in[4];
    const float* a2 = (const float*)d_in[5];
    const float* Wg = (const float*)d_in[6];
    const float* bg = (const float*)d_in[7];

    float* out = (float*)d_out;
    float* fc2 = out + (size_t)Bn * Nn;
    float* g2  = fc2 + (size_t)Bn * Nn * Nn;

    float *h1, *g1, *h2, *el, *er, *sb, *vv;
    cudaGetSymbolAddress((void**)&h1, g_h1);
    cudaGetSymbolAddress((void**)&g1, g_g1);
    cudaGetSymbolAddress((void**)&h2, g_h2);
    cudaGetSymbolAddress((void**)&el, g_el);
    cudaGetSymbolAddress((void**)&er, g_er);
    cudaGetSymbolAddress((void**)&sb, g_sb);
    cudaGetSymbolAddress((void**)&vv, g_v);

    const int M = Bn * Nn;   // 32768

    // 1) h1 = x @ W1
    gemm_kernel<<<dim3(H1n / 128, M / 128), 256>>>(x, W1, h1, M, H1n, FIN);
    // 2) el1/er1
    eler_kernel<<<M / 8, 256>>>(h1, a1, el, er, H1n);
    // 3) per-batch scale/bias
    minmax_kernel<<<Bn, 256>>>(el, er, sb);
    // 4) g1 = elu(att1 @ h1)   [FFMA2]
    fused_att1_kernel<<<dim3(Nn / 64, H1n / 128, Bn), 256>>>(h1, el, er, sb, g1);
    // 5) h2 = g1 @ W2
    gemm_kernel<<<dim3(H2n / 128, M / 128), 256>>>(g1, W2, h2, M, H2n, H1n);
    // 6) el2/er2
    eler_kernel<<<M / 8, 256>>>(h2, a2, el, er, H2n);
    // 7) scale/bias
    minmax_kernel<<<Bn, 256>>>(el, er, sb);
    // 8) fc2 + g2 = att2 @ h2   [FFMA2]
    fused_att2_kernel<<<dim3(Nn / 64, Bn), 256>>>(h2, el, er, sb, fc2, g2);
    // 9) v = g2 @ Wg
    v_kernel<<<M / 8, 256>>>(g2, Wg, vv);
    // 10) out = leaky(fc2 @ v + bg)
    z_kernel<<<M, 256>>>(fc2, vv, bg, out);
}

// round 10
// speedup vs baseline: 1.3844x; 1.3844x over previous
#include <cuda_runtime.h>
#include <math.h>

#define Bn   32
#define Nn   1024
#define FIN  512
#define H1n  256
#define H2n  128

// ---- scratch (device globals; no allocation allowed) ----
__device__ float g_h1[Bn * Nn * H1n];   // 32 MB
__device__ float g_g1[Bn * Nn * H1n];   // 32 MB
__device__ float g_h2[Bn * Nn * H2n];   // 16 MB
__device__ float g_el[Bn * Nn];
__device__ float g_er[Bn * Nn];
__device__ float g_sb[Bn * 2];          // per-batch (scale, bias)
__device__ float g_v[Bn * Nn];          // g2 @ Wg

// ============================================================
// fp32 GEMM: C[M,N] = A[M,K] * B[K,N]   (R5/R6 version, known good)
// BM=128, BN=128, BK=8, 256 threads, 8x8 per thread
// ============================================================
__global__ __launch_bounds__(256) void gemm_kernel(
    const float* __restrict__ A, const float* __restrict__ B,
    float* __restrict__ C, int M, int N, int K)
{
    __shared__ float As[8][132];
    __shared__ float Bs[8][128];
    int t = threadIdx.x;
    int bm = blockIdx.y * 128, bn = blockIdx.x * 128;
    int tx = t & 15, ty = t >> 4;
    int trow = ty * 8;
    int tc0 = tx * 4;

    float acc[8][8];
#pragma unroll
    for (int i = 0; i < 8; i++)
#pragma unroll
        for (int j = 0; j < 8; j++) acc[i][j] = 0.f;

    int arow = t >> 1, ak = (t & 1) * 4;
    int bk = t >> 5, bcol = (t & 31) * 4;

    for (int k0 = 0; k0 < K; k0 += 8) {
        float4 av = *(const float4*)&A[(size_t)(bm + arow) * K + k0 + ak];
        As[ak + 0][arow] = av.x; As[ak + 1][arow] = av.y;
        As[ak + 2][arow] = av.z; As[ak + 3][arow] = av.w;
        *(float4*)&Bs[bk][bcol] = *(const float4*)&B[(size_t)(k0 + bk) * N + bn + bcol];
        __syncthreads();
#pragma unroll
        for (int kk = 0; kk < 8; kk++) {
            float4 a0 = *(const float4*)&As[kk][trow];
            float4 a1 = *(const float4*)&As[kk][trow + 4];
            float4 b0 = *(const float4*)&Bs[kk][tc0];
            float4 b1 = *(const float4*)&Bs[kk][tc0 + 64];
            float ar[8] = {a0.x, a0.y, a0.z, a0.w, a1.x, a1.y, a1.z, a1.w};
#pragma unroll
            for (int ii = 0; ii < 8; ii++) {
                acc[ii][0] += ar[ii] * b0.x;
                acc[ii][1] += ar[ii] * b0.y;
                acc[ii][2] += ar[ii] * b0.z;
                acc[ii][3] += ar[ii] * b0.w;
                acc[ii][4] += ar[ii] * b1.x;
                acc[ii][5] += ar[ii] * b1.y;
                acc[ii][6] += ar[ii] * b1.z;
                acc[ii][7] += ar[ii] * b1.w;
            }
        }
        __syncthreads();
    }
#pragma unroll
    for (int ii = 0; ii < 8; ii++) {
        float* cr = &C[(size_t)(bm + trow + ii) * N + bn];
        *(float4*)&cr[tc0]      = make_float4(acc[ii][0], acc[ii][1], acc[ii][2], acc[ii][3]);
        *(float4*)&cr[tc0 + 64] = make_float4(acc[ii][4], acc[ii][5], acc[ii][6], acc[ii][7]);
    }
}

// ============================================================
// el/er: per row dot with a[0:Fo] and a[Fo:2Fo]. One warp/row.
// ============================================================
__global__ __launch_bounds__(256) void eler_kernel(
    const float* __restrict__ h, const float* __restrict__ a,
    float* __restrict__ el, float* __restrict__ er, int Fo)
{
    int row = (blockIdx.x * blockDim.x + threadIdx.x) >> 5;
    int lane = threadIdx.x & 31;
    if (row >= Bn * Nn) return;
    const float* hr = h + (size_t)row * Fo;
    float sl = 0.f, sr = 0.f;
    for (int f = lane; f < Fo; f += 32) {
        float hv = hr[f];
        sl += hv * a[f];
        sr += hv * a[Fo + f];
    }
#pragma unroll
    for (int o = 16; o; o >>= 1) {
        sl += __shfl_xor_sync(0xffffffffu, sl, o);
        sr += __shfl_xor_sync(0xffffffffu, sr, o);
    }
    if (lane == 0) { el[row] = sl; er[row] = sr; }
}

// ============================================================
// per-batch min/max of el, er -> (scale, bias)
// ============================================================
__global__ __launch_bounds__(256) void minmax_kernel(
    const float* __restrict__ el, const float* __restrict__ er,
    float* __restrict__ sb)
{
    int b = blockIdx.x, t = threadIdx.x;
    const float* e1 = el + b * Nn;
    const float* e2 = er + b * Nn;
    float mnl = 1e30f, mxl = -1e30f, mnr = 1e30f, mxr = -1e30f;
    for (int i = t; i < Nn; i += 256) {
        float a = e1[i]; mnl = fminf(mnl, a); mxl = fmaxf(mxl, a);
        float c = e2[i]; mnr = fminf(mnr, c); mxr = fmaxf(mxr, c);
    }
#pragma unroll
    for (int o = 16; o; o >>= 1) {
        mnl = fminf(mnl, __shfl_xor_sync(0xffffffffu, mnl, o));
        mxl = fmaxf(mxl, __shfl_xor_sync(0xffffffffu, mxl, o));
        mnr = fminf(mnr, __shfl_xor_sync(0xffffffffu, mnr, o));
        mxr = fmaxf(mxr, __shfl_xor_sync(0xffffffffu, mxr, o));
    }
    __shared__ float s[8][4];
    int w = t >> 5, lane = t & 31;
    if (lane == 0) { s[w][0] = mnl; s[w][1] = mxl; s[w][2] = mnr; s[w][3] = mxr; }
    __syncthreads();
    if (t == 0) {
#pragma unroll
        for (int i = 1; i < 8; i++) {
            mnl = fminf(mnl, s[i][0]); mxl = fmaxf(mxl, s[i][1]);
            mnr = fminf(mnr, s[i][2]); mxr = fmaxf(mxr, s[i][3]);
        }
        float emin = mnl + mnr; emin = emin >= 0.f ? emin : 0.01f * emin;
        float emax = mxl + mxr; emax = emax >= 0.f ? emax : 0.01f * emax;
        float sc = 30.f / (emax - emin);
        sb[b * 2] = sc;
        sb[b * 2 + 1] = -emin * sc - 20.f;
    }
}

// ============================================================
// Fused attention GEMM, double-buffered, single sync per tile.
// Tile: 64 i x 128 f per block, 256 threads, 8i x 4f per thread.
//   out[b,i,f] = act( sum_j sigmoid(scale*leaky(el_i+er_j)+bias) * h[b,j,f] )
// ELU: apply elu on output (layer 1).  WFC2: also write att tile to fc2.
// smem: hs 2x(32x128) = 32KB, atts 2x(64x32) = 16KB  (48KB total)
// Inner mix: per 4-jj quad = 8 LDS.128(att bcast) + 4 LDS.128(h) + 128 FFMA.
// ============================================================
template<int FH, bool ELU, bool WFC2>
__global__ __launch_bounds__(256, 2) void fused_att_kernel(
    const float* __restrict__ h, const float* __restrict__ el,
    const float* __restrict__ er, const float* __restrict__ sb,
    float* __restrict__ outp, float* __restrict__ fc2)
{
    __shared__ float hs[2][32][128];
    __shared__ float atts[2][64][32];
    int b = blockIdx.z;
    int i0 = blockIdx.x * 64;
    int f0 = blockIdx.y * 128;
    int t = threadIdx.x;
    float scale = sb[b * 2], bias = sb[b * 2 + 1];
    int fc0 = (t & 31) * 4;          // 4 f columns
    int ir0 = (t >> 5) * 8;          // warp-uniform i base (atts broadcast)
    int arow = t >> 2;               // sigmoid row 0..63
    int jbase = (t & 3) * 8;         // 8 j per thread

    const float* hb = h + (size_t)b * Nn * FH + f0;
    const float* erb = er + b * Nn;
    float eli = el[b * Nn + i0 + arow];

    float acc[8][4];
#pragma unroll
    for (int i = 0; i < 8; i++)
#pragma unroll
        for (int q = 0; q < 4; q++) acc[i][q] = 0.f;

    // register prefetch of tile 0
    float4 hreg[4];
    float4 e4a, e4b;
#pragma unroll
    for (int r = 0; r < 4; r++) {
        int idx = t + r * 256;
        int jj = idx >> 5, fq = (idx & 31) * 4;
        hreg[r] = *(const float4*)&hb[(size_t)jj * FH + fq];
    }
    e4a = *(const float4*)&erb[jbase];
    e4b = *(const float4*)&erb[jbase + 4];

    int s = 0;
    for (int j0 = 0; j0 < Nn; j0 += 32) {
        // ---- store phase (buffer s) ----
#pragma unroll
        for (int r = 0; r < 4; r++) {
            int idx = t + r * 256;
            int jj = idx >> 5, fq = (idx & 31) * 4;
            *(float4*)&hs[s][jj][fq] = hreg[r];
        }
        float ee[8] = {e4a.x, e4a.y, e4a.z, e4a.w, e4b.x, e4b.y, e4b.z, e4b.w};
        float av[8];
#pragma unroll
        for (int r = 0; r < 8; r++) {
            float x = eli + ee[r];
            x = x >= 0.f ? x : 0.01f * x;
            x = scale * x + bias;
            av[r] = 1.f / (1.f + __expf(-x));
        }
        *(float4*)&atts[s][arow][jbase]     = make_float4(av[0], av[1], av[2], av[3]);
        *(float4*)&atts[s][arow][jbase + 4] = make_float4(av[4], av[5], av[6], av[7]);
        if (WFC2) {
            float* fr = fc2 + (size_t)(b * Nn + i0 + arow) * Nn + j0 + jbase;
            *(float4*)&fr[0] = make_float4(av[0], av[1], av[2], av[3]);
            *(float4*)&fr[4] = make_float4(av[4], av[5], av[6], av[7]);
        }
        __syncthreads();
        // ---- prefetch next tile ----
        if (j0 + 32 < Nn) {
            const float* hbn = hb + (size_t)(j0 + 32) * FH;
#pragma unroll
            for (int r = 0; r < 4; r++) {
                int idx = t + r * 256;
                int jj = idx >> 5, fq = (idx & 31) * 4;
                hreg[r] = *(const float4*)&hbn[(size_t)jj * FH + fq];
            }
            e4a = *(const float4*)&erb[j0 + 32 + jbase];
            e4b = *(const float4*)&erb[j0 + 32 + jbase + 4];
        }
        // ---- compute phase (buffer s) ----
#pragma unroll
        for (int q = 0; q < 8; q++) {
            float4 a4[8];
#pragma unroll
            for (int ii = 0; ii < 8; ii++)
                a4[ii] = *(const float4*)&atts[s][ir0 + ii][q * 4];
#pragma unroll
            for (int p = 0; p < 4; p++) {
                float4 h4 = *(const float4*)&hs[s][q * 4 + p][fc0];
#pragma unroll
                for (int ii = 0; ii < 8; ii++) {
                    float a = (p == 0) ? a4[ii].x : (p == 1) ? a4[ii].y
                            : (p == 2) ? a4[ii].z : a4[ii].w;
                    acc[ii][0] += a * h4.x;
                    acc[ii][1] += a * h4.y;
                    acc[ii][2] += a * h4.z;
                    acc[ii][3] += a * h4.w;
                }
            }
        }
        s ^= 1;   // single sync per tile: double buffer makes this safe
    }
    float* ob = outp + (size_t)b * Nn * FH + f0;
#pragma unroll
    for (int ii = 0; ii < 8; ii++) {
        float4 v;
        if (ELU) {
            v.x = acc[ii][0] > 0.f ? acc[ii][0] : __expf(acc[ii][0]) - 1.f;
            v.y = acc[ii][1] > 0.f ? acc[ii][1] : __expf(acc[ii][1]) - 1.f;
            v.z = acc[ii][2] > 0.f ? acc[ii][2] : __expf(acc[ii][2]) - 1.f;
            v.w = acc[ii][3] > 0.f ? acc[ii][3] : __expf(acc[ii][3]) - 1.f;
        } else {
            v = make_float4(acc[ii][0], acc[ii][1], acc[ii][2], acc[ii][3]);
        }
        *(float4*)&ob[(size_t)(i0 + ir0 + ii) * FH + fc0] = v;
    }
}

// ============================================================
// v[b,j] = g2[b,j,:] . Wg  (one warp per row)
// ============================================================
__global__ __launch_bounds__(256) void v_kernel(
    const float* __restrict__ g2, const float* __restrict__ Wg,
    float* __restrict__ v)
{
    int row = (blockIdx.x * blockDim.x + threadIdx.x) >> 5;
    int lane = threadIdx.x & 31;
    if (row >= Bn * Nn) return;
    const float* g = g2 + (size_t)row * H2n;
    float s = 0.f;
#pragma unroll
    for (int f = lane; f < H2n; f += 32) s += g[f] * Wg[f];
#pragma unroll
    for (int o = 16; o; o >>= 1) s += __shfl_xor_sync(0xffffffffu, s, o);
    if (lane == 0) v[row] = s;
}

// ============================================================
// out[b,i] = leaky( sum_j fc2[b,i,j]*v[b,j] + bg, 0.01 )
// ============================================================
__global__ __launch_bounds__(256) void z_kernel(
    const float* __restrict__ fc2, const float* __restrict__ v,
    const float* __restrict__ bg, float* __restrict__ out)
{
    int row = blockIdx.x;
    int b = row >> 10;
    int t = threadIdx.x;
    const float* fr = fc2 + (size_t)row * Nn;
    const float* vb = v + b * Nn;
    float4 f4 = *(const float4*)&fr[t * 4];
    float4 v4 = *(const float4*)&vb[t * 4];
    float s = f4.x * v4.x + f4.y * v4.y + f4.z * v4.z + f4.w * v4.w;
#pragma unroll
    for (int o = 16; o; o >>= 1) s += __shfl_xor_sync(0xffffffffu, s, o);
    __shared__ float red[8];
    int w = t >> 5, lane = t & 31;
    if (lane == 0) red[w] = s;
    __syncthreads();
    if (t == 0) {
        float z = red[0] + red[1] + red[2] + red[3]
                + red[4] + red[5] + red[6] + red[7] + bg[0];
        out[row] = z >= 0.f ? z : 0.01f * z;
    }
}

// ============================================================
extern "C" void kernel_launch(void* const* d_in, const int* in_sizes, int n_in,
                              void* d_out, int out_size)
{
    const float* x  = (const float*)d_in[0];
    // d_in[1] = edge_weight (unused by reference)
    const float* W1 = (const float*)d_in[2];
    const float* a1 = (const float*)d_in[3];
    const float* W2 = (const float*)d_in[4];
    const float* a2 = (const float*)d_in[5];
    const float* Wg = (const float*)d_in[6];
    const float* bg = (const float*)d_in[7];

    float* out = (float*)d_out;
    float* fc2 = out + (size_t)Bn * Nn;
    float* g2  = fc2 + (size_t)Bn * Nn * Nn;

    float *h1, *g1, *h2, *el, *er, *sb, *vv;
    cudaGetSymbolAddress((void**)&h1, g_h1);
    cudaGetSymbolAddress((void**)&g1, g_g1);
    cudaGetSymbolAddress((void**)&h2, g_h2);
    cudaGetSymbolAddress((void**)&el, g_el);
    cudaGetSymbolAddress((void**)&er, g_er);
    cudaGetSymbolAddress((void**)&sb, g_sb);
    cudaGetSymbolAddress((void**)&vv, g_v);

    const int M = Bn * Nn;   // 32768

    // 1) h1 = x @ W1
    gemm_kernel<<<dim3(H1n / 128, M / 128), 256>>>(x, W1, h1, M, H1n, FIN);
    // 2) el1/er1
    eler_kernel<<<M / 8, 256>>>(h1, a1, el, er, H1n);
    // 3) per-batch scale/bias
    minmax_kernel<<<Bn, 256>>>(el, er, sb);
    // 4) g1 = elu(att1 @ h1)
    fused_att_kernel<H1n, true, false>
        <<<dim3(Nn / 64, H1n / 128, Bn), 256>>>(h1, el, er, sb, g1, nullptr);
    // 5) h2 = g1 @ W2
    gemm_kernel<<<dim3(H2n / 128, M / 128), 256>>>(g1, W2, h2, M, H2n, H1n);
    // 6) el2/er2
    eler_kernel<<<M / 8, 256>>>(h2, a2, el, er, H2n);
    // 7) scale/bias
    minmax_kernel<<<Bn, 256>>>(el, er, sb);
    // 8) fc2 + g2 = att2 @ h2
    fused_att_kernel<H2n, false, true>
        <<<dim3(Nn / 64, 1, Bn), 256>>>(h2, el, er, sb, g2, fc2);
    // 9) v = g2 @ Wg
    v_kernel<<<M / 8, 256>>>(g2, Wg, vv);
    // 10) out = leaky(fc2 @ v + bg)
    z_kernel<<<M, 256>>>(fc2, vv, bg, out);
}

// round 12
// speedup vs baseline: 1.9833x; 1.4326x over previous
#include <cuda_runtime.h>
#include <cuda_bf16.h>
#include <math.h>
#include <stdint.h>

#define Bn   32
#define Nn   1024
#define FIN  512
#define H1n  256
#define H2n  128

// ---- scratch (device globals; no allocation allowed) ----
__device__ float g_h1[Bn * Nn * H1n];
__device__ float g_g1[Bn * Nn * H1n];
__device__ float g_h2[Bn * Nn * H2n];
__device__ __nv_bfloat16 g_h1h[Bn * Nn * H1n];
__device__ __nv_bfloat16 g_h1l[Bn * Nn * H1n];
__device__ __nv_bfloat16 g_h2h[Bn * Nn * H2n];
__device__ __nv_bfloat16 g_h2l[Bn * Nn * H2n];
__device__ float g_el[Bn * Nn];
__device__ float g_er[Bn * Nn];
__device__ float g_sb[Bn * 2];
__device__ float g_v[Bn * Nn];

// ============================================================
// warp-MMA helpers (sm_80-era PTX: valid at compute_103)
// ============================================================
__device__ __forceinline__ uint32_t smem_u32(const void* p) {
    uint32_t a;
    asm("{ .reg .u64 t; cvta.to.shared.u64 t, %1; cvt.u32.u64 %0, t; }"
        : "=r"(a) : "l"(p));
    return a;
}
__device__ __forceinline__ void ldsm4(uint32_t* r, uint32_t addr) {
    asm volatile("ldmatrix.sync.aligned.m8n8.x4.shared.b16 {%0,%1,%2,%3}, [%4];"
        : "=r"(r[0]), "=r"(r[1]), "=r"(r[2]), "=r"(r[3]) : "r"(addr));
}
__device__ __forceinline__ void ldsm4t(uint32_t* r, uint32_t addr) {
    asm volatile("ldmatrix.sync.aligned.m8n8.x4.trans.shared.b16 {%0,%1,%2,%3}, [%4];"
        : "=r"(r[0]), "=r"(r[1]), "=r"(r[2]), "=r"(r[3]) : "r"(addr));
}
__device__ __forceinline__ void mma16816(float* d, const uint32_t* a, const uint32_t* b) {
    asm volatile(
        "mma.sync.aligned.m16n8k16.row.col.f32.bf16.bf16.f32 "
        "{%0,%1,%2,%3}, {%4,%5,%6,%7}, {%8,%9}, {%0,%1,%2,%3};"
        : "+f"(d[0]), "+f"(d[1]), "+f"(d[2]), "+f"(d[3])
        : "r"(a[0]), "r"(a[1]), "r"(a[2]), "r"(a[3]), "r"(b[0]), "r"(b[1]));
}

// ============================================================
// fp32 GEMM: C[M,N] = A[M,K] * B[K,N]   (known-good SIMT)
// ============================================================
__global__ __launch_bounds__(256) void gemm_kernel(
    const float* __restrict__ A, const float* __restrict__ B,
    float* __restrict__ C, int M, int N, int K)
{
    __shared__ float As[8][132];
    __shared__ float Bs[8][128];
    int t = threadIdx.x;
    int bm = blockIdx.y * 128, bn = blockIdx.x * 128;
    int tx = t & 15, ty = t >> 4;
    int trow = ty * 8;
    int tc0 = tx * 4;

    float acc[8][8];
#pragma unroll
    for (int i = 0; i < 8; i++)
#pragma unroll
        for (int j = 0; j < 8; j++) acc[i][j] = 0.f;

    int arow = t >> 1, ak = (t & 1) * 4;
    int bk = t >> 5, bcol = (t & 31) * 4;

    for (int k0 = 0; k0 < K; k0 += 8) {
        float4 av = *(const float4*)&A[(size_t)(bm + arow) * K + k0 + ak];
        As[ak + 0][arow] = av.x; As[ak + 1][arow] = av.y;
        As[ak + 2][arow] = av.z; As[ak + 3][arow] = av.w;
        *(float4*)&Bs[bk][bcol] = *(const float4*)&B[(size_t)(k0 + bk) * N + bn + bcol];
        __syncthreads();
#pragma unroll
        for (int kk = 0; kk < 8; kk++) {
            float4 a0 = *(const float4*)&As[kk][trow];
            float4 a1 = *(const float4*)&As[kk][trow + 4];
            float4 b0 = *(const float4*)&Bs[kk][tc0];
            float4 b1 = *(const float4*)&Bs[kk][tc0 + 64];
            float ar[8] = {a0.x, a0.y, a0.z, a0.w, a1.x, a1.y, a1.z, a1.w};
#pragma unroll
            for (int ii = 0; ii < 8; ii++) {
                acc[ii][0] += ar[ii] * b0.x;
                acc[ii][1] += ar[ii] * b0.y;
                acc[ii][2] += ar[ii] * b0.z;
                acc[ii][3] += ar[ii] * b0.w;
                acc[ii][4] += ar[ii] * b1.x;
                acc[ii][5] += ar[ii] * b1.y;
                acc[ii][6] += ar[ii] * b1.z;
                acc[ii][7] += ar[ii] * b1.w;
            }
        }
        __syncthreads();
    }
#pragma unroll
    for (int ii = 0; ii < 8; ii++) {
        float* cr = &C[(size_t)(bm + trow + ii) * N + bn];
        *(float4*)&cr[tc0]      = make_float4(acc[ii][0], acc[ii][1], acc[ii][2], acc[ii][3]);
        *(float4*)&cr[tc0 + 64] = make_float4(acc[ii][4], acc[ii][5], acc[ii][6], acc[ii][7]);
    }
}

// ============================================================
// el/er
// ============================================================
__global__ __launch_bounds__(256) void eler_kernel(
    const float* __restrict__ h, const float* __restrict__ a,
    float* __restrict__ el, float* __restrict__ er, int Fo)
{
    int row = (blockIdx.x * blockDim.x + threadIdx.x) >> 5;
    int lane = threadIdx.x & 31;
    if (row >= Bn * Nn) return;
    const float* hr = h + (size_t)row * Fo;
    float sl = 0.f, sr = 0.f;
    for (int f = lane; f < Fo; f += 32) {
        float hv = hr[f];
        sl += hv * a[f];
        sr += hv * a[Fo + f];
    }
#pragma unroll
    for (int o = 16; o; o >>= 1) {
        sl += __shfl_xor_sync(0xffffffffu, sl, o);
        sr += __shfl_xor_sync(0xffffffffu, sr, o);
    }
    if (lane == 0) { el[row] = sl; er[row] = sr; }
}

// ============================================================
// per-batch min/max -> (scale, bias)
// ============================================================
__global__ __launch_bounds__(256) void minmax_kernel(
    const float* __restrict__ el, const float* __restrict__ er,
    float* __restrict__ sb)
{
    int b = blockIdx.x, t = threadIdx.x;
    const float* e1 = el + b * Nn;
    const float* e2 = er + b * Nn;
    float mnl = 1e30f, mxl = -1e30f, mnr = 1e30f, mxr = -1e30f;
    for (int i = t; i < Nn; i += 256) {
        float a = e1[i]; mnl = fminf(mnl, a); mxl = fmaxf(mxl, a);
        float c = e2[i]; mnr = fminf(mnr, c); mxr = fmaxf(mxr, c);
    }
#pragma unroll
    for (int o = 16; o; o >>= 1) {
        mnl = fminf(mnl, __shfl_xor_sync(0xffffffffu, mnl, o));
        mxl = fmaxf(mxl, __shfl_xor_sync(0xffffffffu, mxl, o));
        mnr = fminf(mnr, __shfl_xor_sync(0xffffffffu, mnr, o));
        mxr = fmaxf(mxr, __shfl_xor_sync(0xffffffffu, mxr, o));
    }
    __shared__ float s[8][4];
    int w = t >> 5, lane = t & 31;
    if (lane == 0) { s[w][0] = mnl; s[w][1] = mxl; s[w][2] = mnr; s[w][3] = mxr; }
    __syncthreads();
    if (t == 0) {
#pragma unroll
        for (int i = 1; i < 8; i++) {
            mnl = fminf(mnl, s[i][0]); mxl = fmaxf(mxl, s[i][1]);
            mnr = fminf(mnr, s[i][2]); mxr = fmaxf(mxr, s[i][3]);
        }
        float emin = mnl + mnr; emin = emin >= 0.f ? emin : 0.01f * emin;
        float emax = mxl + mxr; emax = emax >= 0.f ? emax : 0.01f * emax;
        float sc = 30.f / (emax - emin);
        sb[b * 2] = sc;
        sb[b * 2 + 1] = -emin * sc - 20.f;
    }
}

// ============================================================
// fp32 -> bf16 hi/lo split (preconvert h)
// ============================================================
__global__ __launch_bounds__(256) void split_kernel(
    const float* __restrict__ src, __nv_bfloat16* __restrict__ hi,
    __nv_bfloat16* __restrict__ lo, int n4)
{
    int i = blockIdx.x * blockDim.x + threadIdx.x;
    if (i >= n4) return;
    float4 v = ((const float4*)src)[i];
    float vs[4] = {v.x, v.y, v.z, v.w};
    __nv_bfloat162 hp[2], lp[2];
#pragma unroll
    for (int p = 0; p < 2; p++) {
        __nv_bfloat16 h0 = __float2bfloat16_rn(vs[p * 2]);
        __nv_bfloat16 h1 = __float2bfloat16_rn(vs[p * 2 + 1]);
        __nv_bfloat16 l0 = __float2bfloat16_rn(vs[p * 2]     - __bfloat162float(h0));
        __nv_bfloat16 l1 = __float2bfloat16_rn(vs[p * 2 + 1] - __bfloat162float(h1));
        hp[p].x = h0; hp[p].y = h1;
        lp[p].x = l0; lp[p].y = l1;
    }
    ((__nv_bfloat162*)hi)[i * 2]     = hp[0];
    ((__nv_bfloat162*)hi)[i * 2 + 1] = hp[1];
    ((__nv_bfloat162*)lo)[i * 2]     = lp[0];
    ((__nv_bfloat162*)lo)[i * 2 + 1] = lp[1];
}

// ============================================================
// Tensor-core fused attention GEMM (warp mma.sync, split-bf16):
//   out[b,i,f] = act( sum_j sigmoid(scale*leaky(el_i+er_j)+bias) * h[b,j,f] )
// CTA: 128 i x 128 f; 8 warps, warp tile 32i x 64f; K chunks of 32 j.
// acc = Ahi*Bhi + Alo*Bhi + Ahi*Blo  (fp32 accum; dropped term ~2^-18)
// A SMEM: [128][40] bf16 (pad 40 -> conflict-free ldmatrix, 80B rows)
// B SMEM: [32][136] bf16 (pad 136 -> 272B rows, conflict-free trans ldmatrix)
// ============================================================
template<int FH, bool ELU, bool WFC2>
__global__ __launch_bounds__(256) void att_mma_kernel(
    const float* __restrict__ el, const float* __restrict__ er,
    const float* __restrict__ sb,
    const __nv_bfloat16* __restrict__ hh, const __nv_bfloat16* __restrict__ hl,
    float* __restrict__ outp, float* __restrict__ fc2)
{
    __shared__ __nv_bfloat16 a_hi[128][40];
    __shared__ __nv_bfloat16 a_lo[128][40];
    __shared__ __nv_bfloat16 b_hi[32][136];
    __shared__ __nv_bfloat16 b_lo[32][136];

    const int t  = threadIdx.x;
    const int b  = blockIdx.z;
    const int i0 = blockIdx.x * 128;
    const int f0 = blockIdx.y * 128;
    const int w  = t >> 5, l = t & 31;
    const int wi0 = (w & 3) * 32;        // warp i-offset
    const int wf0 = (w >> 2) * 64;       // warp f-offset

    const float scale = sb[b * 2], bias = sb[b * 2 + 1];
    const float* erb = er + b * Nn;
    const int ai = t >> 1, aj = (t & 1) * 16;   // att compute mapping
    const float eli = el[b * Nn + i0 + ai];

    const int bj = t >> 3, bf = (t & 7) * 16;   // B tile load mapping
    const __nv_bfloat16* hhb = hh + (size_t)b * Nn * FH + f0;
    const __nv_bfloat16* hlb = hl + (size_t)b * Nn * FH + f0;

    float acc[2][8][4];
#pragma unroll
    for (int m = 0; m < 2; m++)
#pragma unroll
        for (int n = 0; n < 8; n++)
#pragma unroll
            for (int q = 0; q < 4; q++) acc[m][n][q] = 0.f;

    const uint32_t aH = smem_u32(a_hi), aL = smem_u32(a_lo);
    const uint32_t bH = smem_u32(b_hi), bL = smem_u32(b_lo);
    const uint32_t lrow = (uint32_t)(l & 15), lhalf = (uint32_t)(l >> 4);

    for (int ch = 0; ch < Nn / 32; ch++) {
        const int j0 = ch * 32;
        // ---- attention values (exact fp32 sigmoid) ----
        float sv[16];
#pragma unroll
        for (int u = 0; u < 4; u++) {
            float4 e4 = *(const float4*)&erb[j0 + aj + u * 4];
            float xs[4] = {e4.x, e4.y, e4.z, e4.w};
#pragma unroll
            for (int q = 0; q < 4; q++) {
                float x = eli + xs[q];
                x = x >= 0.f ? x : 0.01f * x;
                x = scale * x + bias;
                sv[u * 4 + q] = 1.f / (1.f + __expf(-x));
            }
        }
        if (WFC2) {
            float* fr = fc2 + ((size_t)(b * Nn + i0 + ai)) * Nn + j0 + aj;
#pragma unroll
            for (int u = 0; u < 4; u++)
                *(float4*)&fr[u * 4] =
                    make_float4(sv[u*4], sv[u*4+1], sv[u*4+2], sv[u*4+3]);
        }
        // split att to bf16 hi/lo and store A tiles
        {
            uint32_t hw[8], lw[8];
#pragma unroll
            for (int p = 0; p < 8; p++) {
                float v0 = sv[p * 2], v1 = sv[p * 2 + 1];
                __nv_bfloat162 hp, lp;
                hp.x = __float2bfloat16_rn(v0);
                hp.y = __float2bfloat16_rn(v1);
                lp.x = __float2bfloat16_rn(v0 - __bfloat162float(hp.x));
                lp.y = __float2bfloat16_rn(v1 - __bfloat162float(hp.y));
                hw[p] = *(uint32_t*)&hp;
                lw[p] = *(uint32_t*)&lp;
            }
            *(uint4*)&a_hi[ai][aj]     = make_uint4(hw[0], hw[1], hw[2], hw[3]);
            *(uint4*)&a_hi[ai][aj + 8] = make_uint4(hw[4], hw[5], hw[6], hw[7]);
            *(uint4*)&a_lo[ai][aj]     = make_uint4(lw[0], lw[1], lw[2], lw[3]);
            *(uint4*)&a_lo[ai][aj + 8] = make_uint4(lw[4], lw[5], lw[6], lw[7]);
        }
        // ---- B tiles from preconverted global bf16 ----
        {
            const __nv_bfloat16* sh = hhb + (size_t)(j0 + bj) * FH + bf;
            const __nv_bfloat16* sl = hlb + (size_t)(j0 + bj) * FH + bf;
            *(uint4*)&b_hi[bj][bf]     = *(const uint4*)sh;
            *(uint4*)&b_hi[bj][bf + 8] = *(const uint4*)(sh + 8);
            *(uint4*)&b_lo[bj][bf]     = *(const uint4*)sl;
            *(uint4*)&b_lo[bj][bf + 8] = *(const uint4*)(sl + 8);
        }
        __syncthreads();
        // ---- warp MMA: 2 k-steps of 16 ----
#pragma unroll
        for (int ks = 0; ks < 2; ks++) {
            uint32_t ah[2][4], al2[2][4];
            uint32_t abase = (uint32_t)((wi0 + lrow) * 80 + ks * 32 + lhalf * 16);
            ldsm4(ah[0],  aH + abase);
            ldsm4(ah[1],  aH + abase + 16 * 80);
            ldsm4(al2[0], aL + abase);
            ldsm4(al2[1], aL + abase + 16 * 80);
#pragma unroll
            for (int nb2 = 0; nb2 < 4; nb2++) {
                uint32_t b4h[4], b4l[4];
                uint32_t ba = (uint32_t)((ks * 16 + lrow) * 272
                             + (wf0 + nb2 * 16) * 2 + lhalf * 16);
                ldsm4t(b4h, bH + ba);
                ldsm4t(b4l, bL + ba);
#pragma unroll
                for (int half = 0; half < 2; half++) {
                    int n = nb2 * 2 + half;
                    mma16816(acc[0][n], ah[0],  &b4h[half * 2]);
                    mma16816(acc[1][n], ah[1],  &b4h[half * 2]);
                    mma16816(acc[0][n], al2[0], &b4h[half * 2]);
                    mma16816(acc[1][n], al2[1], &b4h[half * 2]);
                    mma16816(acc[0][n], ah[0],  &b4l[half * 2]);
                    mma16816(acc[1][n], ah[1],  &b4l[half * 2]);
                }
            }
        }
        __syncthreads();
    }

    // ---- epilogue ----
    const int r0 = l >> 2, c0 = (l & 3) * 2;
    float* ob = outp + (size_t)b * Nn * FH;
#pragma unroll
    for (int m = 0; m < 2; m++) {
        int row = i0 + wi0 + m * 16 + r0;
#pragma unroll
        for (int n = 0; n < 8; n++) {
            int col = f0 + wf0 + n * 8 + c0;
            float2 v0 = make_float2(acc[m][n][0], acc[m][n][1]);
            float2 v1 = make_float2(acc[m][n][2], acc[m][n][3]);
            if (ELU) {
                v0.x = v0.x > 0.f ? v0.x : __expf(v0.x) - 1.f;
                v0.y = v0.y > 0.f ? v0.y : __expf(v0.y) - 1.f;
                v1.x = v1.x > 0.f ? v1.x : __expf(v1.x) - 1.f;
                v1.y = v1.y > 0.f ? v1.y : __expf(v1.y) - 1.f;
            }
            *(float2*)&ob[(size_t)row * FH + col]       = v0;
            *(float2*)&ob[(size_t)(row + 8) * FH + col] = v1;
        }
    }
}

// ============================================================
// v[b,j] = g2[b,j,:] . Wg
// ============================================================
__global__ __launch_bounds__(256) void v_kernel(
    const float* __restrict__ g2, const float* __restrict__ Wg,
    float* __restrict__ v)
{
    int row = (blockIdx.x * blockDim.x + threadIdx.x) >> 5;
    int lane = threadIdx.x & 31;
    if (row >= Bn * Nn) return;
    const float* g = g2 + (size_t)row * H2n;
    float s = 0.f;
#pragma unroll
    for (int f = lane; f < H2n; f += 32) s += g[f] * Wg[f];
#pragma unroll
    for (int o = 16; o; o >>= 1) s += __shfl_xor_sync(0xffffffffu, s, o);
    if (lane == 0) v[row] = s;
}

// ============================================================
// out[b,i] = leaky( fc2[b,i,:] . v[b,:] + bg )
// ============================================================
__global__ __launch_bounds__(256) void z_kernel(
    const float* __restrict__ fc2, const float* __restrict__ v,
    const float* __restrict__ bg, float* __restrict__ out)
{
    int row = blockIdx.x;
    int b = row >> 10;
    int t = threadIdx.x;
    const float* fr = fc2 + (size_t)row * Nn;
    const float* vb = v + b * Nn;
    float4 f4 = *(const float4*)&fr[t * 4];
    float4 v4 = *(const float4*)&vb[t * 4];
    float s = f4.x * v4.x + f4.y * v4.y + f4.z * v4.z + f4.w * v4.w;
#pragma unroll
    for (int o = 16; o; o >>= 1) s += __shfl_xor_sync(0xffffffffu, s, o);
    __shared__ float red[8];
    int w = t >> 5, lane = t & 31;
    if (lane == 0) red[w] = s;
    __syncthreads();
    if (t == 0) {
        float z = red[0] + red[1] + red[2] + red[3]
                + red[4] + red[5] + red[6] + red[7] + bg[0];
        out[row] = z >= 0.f ? z : 0.01f * z;
    }
}

// ============================================================
extern "C" void kernel_launch(void* const* d_in, const int* in_sizes, int n_in,
                              void* d_out, int out_size)
{
    const float* x  = (const float*)d_in[0];
    // d_in[1] = edge_weight (unused by reference)
    const float* W1 = (const float*)d_in[2];
    const float* a1 = (const float*)d_in[3];
    const float* W2 = (const float*)d_in[4];
    const float* a2 = (const float*)d_in[5];
    const float* Wg = (const float*)d_in[6];
    const float* bg = (const float*)d_in[7];

    float* out = (float*)d_out;
    float* fc2 = out + (size_t)Bn * Nn;
    float* g2  = fc2 + (size_t)Bn * Nn * Nn;

    float *h1, *g1, *h2, *el, *er, *sb, *vv;
    __nv_bfloat16 *h1h, *h1l, *h2h, *h2l;
    cudaGetSymbolAddress((void**)&h1,  g_h1);
    cudaGetSymbolAddress((void**)&g1,  g_g1);
    cudaGetSymbolAddress((void**)&h2,  g_h2);
    cudaGetSymbolAddress((void**)&h1h, g_h1h);
    cudaGetSymbolAddress((void**)&h1l, g_h1l);
    cudaGetSymbolAddress((void**)&h2h, g_h2h);
    cudaGetSymbolAddress((void**)&h2l, g_h2l);
    cudaGetSymbolAddress((void**)&el,  g_el);
    cudaGetSymbolAddress((void**)&er,  g_er);
    cudaGetSymbolAddress((void**)&sb,  g_sb);
    cudaGetSymbolAddress((void**)&vv,  g_v);

    const int M = Bn * Nn;   // 32768

    // 1) h1 = x @ W1
    gemm_kernel<<<dim3(H1n / 128, M / 128), 256>>>(x, W1, h1, M, H1n, FIN);
    // 2) el1/er1 + scale/bias
    eler_kernel<<<M / 8, 256>>>(h1, a1, el, er, H1n);
    minmax_kernel<<<Bn, 256>>>(el, er, sb);
    // 3) split h1 -> bf16 hi/lo
    split_kernel<<<(Bn * Nn * H1n / 4 + 255) / 256, 256>>>(h1, h1h, h1l, Bn * Nn * H1n / 4);
    // 4) g1 = elu(att1 @ h1)   [warp mma, split-bf16]
    att_mma_kernel<H1n, true, false>
        <<<dim3(Nn / 128, H1n / 128, Bn), 256>>>(el, er, sb, h1h, h1l, g1, nullptr);
    // 5) h2 = g1 @ W2
    gemm_kernel<<<dim3(H2n / 128, M / 128), 256>>>(g1, W2, h2, M, H2n, H1n);
    // 6) el2/er2 + scale/bias
    eler_kernel<<<M / 8, 256>>>(h2, a2, el, er, H2n);
    minmax_kernel<<<Bn, 256>>>(el, er, sb);
    // 7) split h2
    split_kernel<<<(Bn * Nn * H2n / 4 + 255) / 256, 256>>>(h2, h2h, h2l, Bn * Nn * H2n / 4);
    // 8) fc2 + g2 = att2 @ h2   [warp mma, split-bf16]
    att_mma_kernel<H2n, false, true>
        <<<dim3(Nn / 128, 1, Bn), 256>>>(el, er, sb, h2h, h2l, g2, fc2);
    // 9) v = g2 @ Wg
    v_kernel<<<M / 8, 256>>>(g2, Wg, vv);
    // 10) out = leaky(fc2 @ v + bg)
    z_kernel<<<M, 256>>>(fc2, vv, bg, out);
}

// round 13
// speedup vs baseline: 2.2255x; 1.1222x over previous
#include <cuda_runtime.h>
#include <cuda_bf16.h>
#include <math.h>
#include <stdint.h>

#define Bn   32
#define Nn   1024
#define FIN  512
#define H1n  256
#define H2n  128

typedef __nv_bfloat16 bf16;
typedef __nv_bfloat162 bf162;

// ---- scratch (device globals; no allocation allowed) ----
__device__ bf16 g_xh[Bn * Nn * FIN];
__device__ bf16 g_xl[Bn * Nn * FIN];
__device__ bf16 g_w1h[FIN * H1n];
__device__ bf16 g_w1l[FIN * H1n];
__device__ bf16 g_w2h[H1n * H2n];
__device__ bf16 g_w2l[H1n * H2n];
__device__ bf16 g_h1h[Bn * Nn * H1n];
__device__ bf16 g_h1l[Bn * Nn * H1n];
__device__ bf16 g_g1h[Bn * Nn * H1n];
__device__ bf16 g_g1l[Bn * Nn * H1n];
__device__ bf16 g_h2h[Bn * Nn * H2n];
__device__ bf16 g_h2l[Bn * Nn * H2n];
__device__ float g_el[Bn * Nn];
__device__ float g_er[Bn * Nn];
__device__ float g_sb[Bn * 2];
__device__ float g_v[Bn * Nn];

// ============================================================
// warp-MMA helpers (sm_80-era PTX: valid at compute_103)
// ============================================================
__device__ __forceinline__ uint32_t smem_u32(const void* p) {
    uint32_t a;
    asm("{ .reg .u64 t; cvta.to.shared.u64 t, %1; cvt.u32.u64 %0, t; }"
        : "=r"(a) : "l"(p));
    return a;
}
__device__ __forceinline__ void ldsm4(uint32_t* r, uint32_t addr) {
    asm volatile("ldmatrix.sync.aligned.m8n8.x4.shared.b16 {%0,%1,%2,%3}, [%4];"
        : "=r"(r[0]), "=r"(r[1]), "=r"(r[2]), "=r"(r[3]) : "r"(addr));
}
__device__ __forceinline__ void ldsm4t(uint32_t* r, uint32_t addr) {
    asm volatile("ldmatrix.sync.aligned.m8n8.x4.trans.shared.b16 {%0,%1,%2,%3}, [%4];"
        : "=r"(r[0]), "=r"(r[1]), "=r"(r[2]), "=r"(r[3]) : "r"(addr));
}
__device__ __forceinline__ void mma16816(float* d, const uint32_t* a, const uint32_t* b) {
    asm volatile(
        "mma.sync.aligned.m16n8k16.row.col.f32.bf16.bf16.f32 "
        "{%0,%1,%2,%3}, {%4,%5,%6,%7}, {%8,%9}, {%0,%1,%2,%3};"
        : "+f"(d[0]), "+f"(d[1]), "+f"(d[2]), "+f"(d[3])
        : "r"(a[0]), "r"(a[1]), "r"(a[2]), "r"(a[3]), "r"(b[0]), "r"(b[1]));
}
__device__ __forceinline__ bf162 split_hi2(float a, float b, bf162& lo) {
    bf162 hi;
    hi.x = __float2bfloat16_rn(a);
    hi.y = __float2bfloat16_rn(b);
    lo.x = __float2bfloat16_rn(a - __bfloat162float(hi.x));
    lo.y = __float2bfloat16_rn(b - __bfloat162float(hi.y));
    return hi;
}

// ============================================================
// fp32 -> bf16 hi/lo split
// ============================================================
__global__ __launch_bounds__(256) void split_kernel(
    const float* __restrict__ src, bf16* __restrict__ hi,
    bf16* __restrict__ lo, int n4)
{
    int i = blockIdx.x * blockDim.x + threadIdx.x;
    if (i >= n4) return;
    float4 v = ((const float4*)src)[i];
    bf162 h0l, h1l2;
    bf162 h0 = split_hi2(v.x, v.y, h0l);
    bf162 h1 = split_hi2(v.z, v.w, h1l2);
    ((bf162*)hi)[i * 2]     = h0;
    ((bf162*)hi)[i * 2 + 1] = h1;
    ((bf162*)lo)[i * 2]     = h0l;
    ((bf162*)lo)[i * 2 + 1] = h1l2;
}

// ============================================================
// Dense GEMM via warp mma, split-bf16 in & out:
//   C[M,N] = A[M,K] @ B[K,N]; writes C as hi/lo bf16 pair.
// CTA 128m x 128n, 8 warps (4m x 2n), warp 32m x 64n, K chunks of 32.
// ============================================================
template<int K>
__global__ __launch_bounds__(256) void mma_gemm_kernel(
    const bf16* __restrict__ Ah, const bf16* __restrict__ Al,
    const bf16* __restrict__ Bh, const bf16* __restrict__ Bl,
    bf16* __restrict__ Ch, bf16* __restrict__ Cl, int N)
{
    __shared__ bf16 a_hi[128][40];
    __shared__ bf16 a_lo[128][40];
    __shared__ bf16 b_hi[32][136];
    __shared__ bf16 b_lo[32][136];

    const int t = threadIdx.x;
    const int bm = blockIdx.y * 128, bn = blockIdx.x * 128;
    const int w = t >> 5, l = t & 31;
    const int wi0 = (w & 3) * 32;
    const int wf0 = (w >> 2) * 64;

    const int ar = t >> 1, ac = (t & 1) * 16;    // A tile load
    const int br = t >> 3, bc = (t & 7) * 16;    // B tile load

    float acc[2][8][4];
#pragma unroll
    for (int m = 0; m < 2; m++)
#pragma unroll
        for (int n = 0; n < 8; n++)
#pragma unroll
            for (int q = 0; q < 4; q++) acc[m][n][q] = 0.f;

    const uint32_t aH = smem_u32(a_hi), aL = smem_u32(a_lo);
    const uint32_t bH = smem_u32(b_hi), bL = smem_u32(b_lo);
    const uint32_t lrow = (uint32_t)(l & 15), lhalf = (uint32_t)(l >> 4);

    for (int k0 = 0; k0 < K; k0 += 32) {
        {
            const bf16* sa = Ah + (size_t)(bm + ar) * K + k0 + ac;
            const bf16* sl2 = Al + (size_t)(bm + ar) * K + k0 + ac;
            *(uint4*)&a_hi[ar][ac]     = *(const uint4*)sa;
            *(uint4*)&a_hi[ar][ac + 8] = *(const uint4*)(sa + 8);
            *(uint4*)&a_lo[ar][ac]     = *(const uint4*)sl2;
            *(uint4*)&a_lo[ar][ac + 8] = *(const uint4*)(sl2 + 8);
        }
        {
            const bf16* sb2 = Bh + (size_t)(k0 + br) * N + bn + bc;
            const bf16* sl2 = Bl + (size_t)(k0 + br) * N + bn + bc;
            *(uint4*)&b_hi[br][bc]     = *(const uint4*)sb2;
            *(uint4*)&b_hi[br][bc + 8] = *(const uint4*)(sb2 + 8);
            *(uint4*)&b_lo[br][bc]     = *(const uint4*)sl2;
            *(uint4*)&b_lo[br][bc + 8] = *(const uint4*)(sl2 + 8);
        }
        __syncthreads();
#pragma unroll
        for (int ks = 0; ks < 2; ks++) {
            uint32_t ah[2][4], al2[2][4];
            uint32_t abase = (uint32_t)((wi0 + lrow) * 80 + ks * 32 + lhalf * 16);
            ldsm4(ah[0],  aH + abase);
            ldsm4(ah[1],  aH + abase + 16 * 80);
            ldsm4(al2[0], aL + abase);
            ldsm4(al2[1], aL + abase + 16 * 80);
#pragma unroll
            for (int nb2 = 0; nb2 < 4; nb2++) {
                uint32_t b4h[4], b4l[4];
                uint32_t ba = (uint32_t)((ks * 16 + lrow) * 272
                             + (wf0 + nb2 * 16) * 2 + lhalf * 16);
                ldsm4t(b4h, bH + ba);
                ldsm4t(b4l, bL + ba);
#pragma unroll
                for (int half = 0; half < 2; half++) {
                    int n = nb2 * 2 + half;
                    mma16816(acc[0][n], ah[0],  &b4h[half * 2]);
                    mma16816(acc[1][n], ah[1],  &b4h[half * 2]);
                    mma16816(acc[0][n], al2[0], &b4h[half * 2]);
                    mma16816(acc[1][n], al2[1], &b4h[half * 2]);
                    mma16816(acc[0][n], ah[0],  &b4l[half * 2]);
                    mma16816(acc[1][n], ah[1],  &b4l[half * 2]);
                }
            }
        }
        __syncthreads();
    }
    // epilogue: split acc -> Ch/Cl
    const int r0 = l >> 2, c0 = (l & 3) * 2;
#pragma unroll
    for (int m = 0; m < 2; m++) {
        int row = bm + wi0 + m * 16 + r0;
#pragma unroll
        for (int n = 0; n < 8; n++) {
            int col = bn + wf0 + n * 8 + c0;
            bf162 lo0, lo1;
            bf162 hi0 = split_hi2(acc[m][n][0], acc[m][n][1], lo0);
            bf162 hi1 = split_hi2(acc[m][n][2], acc[m][n][3], lo1);
            *(bf162*)&Ch[(size_t)row * N + col]       = hi0;
            *(bf162*)&Cl[(size_t)row * N + col]       = lo0;
            *(bf162*)&Ch[(size_t)(row + 8) * N + col] = hi1;
            *(bf162*)&Cl[(size_t)(row + 8) * N + col] = lo1;
        }
    }
}

// ============================================================
// el/er from hi/lo bf16 h. One warp per row.
// ============================================================
__global__ __launch_bounds__(256) void eler_kernel(
    const bf16* __restrict__ hh, const bf16* __restrict__ hl,
    const float* __restrict__ a,
    float* __restrict__ el, float* __restrict__ er, int Fo)
{
    int row = (blockIdx.x * blockDim.x + threadIdx.x) >> 5;
    int lane = threadIdx.x & 31;
    if (row >= Bn * Nn) return;
    const bf16* hr = hh + (size_t)row * Fo;
    const bf16* lr = hl + (size_t)row * Fo;
    float sl = 0.f, sr = 0.f;
    for (int f = lane * 2; f < Fo; f += 64) {
        bf162 h2 = *(const bf162*)&hr[f];
        bf162 l2 = *(const bf162*)&lr[f];
        float2 av = *(const float2*)&a[f];
        float2 bv = *(const float2*)&a[Fo + f];
        float v0 = __bfloat162float(h2.x) + __bfloat162float(l2.x);
        float v1 = __bfloat162float(h2.y) + __bfloat162float(l2.y);
        sl += v0 * av.x + v1 * av.y;
        sr += v0 * bv.x + v1 * bv.y;
    }
#pragma unroll
    for (int o = 16; o; o >>= 1) {
        sl += __shfl_xor_sync(0xffffffffu, sl, o);
        sr += __shfl_xor_sync(0xffffffffu, sr, o);
    }
    if (lane == 0) { el[row] = sl; er[row] = sr; }
}

// ============================================================
// per-batch min/max -> (scale, bias)
// ============================================================
__global__ __launch_bounds__(256) void minmax_kernel(
    const float* __restrict__ el, const float* __restrict__ er,
    float* __restrict__ sb)
{
    int b = blockIdx.x, t = threadIdx.x;
    const float* e1 = el + b * Nn;
    const float* e2 = er + b * Nn;
    float mnl = 1e30f, mxl = -1e30f, mnr = 1e30f, mxr = -1e30f;
    for (int i = t; i < Nn; i += 256) {
        float a = e1[i]; mnl = fminf(mnl, a); mxl = fmaxf(mxl, a);
        float c = e2[i]; mnr = fminf(mnr, c); mxr = fmaxf(mxr, c);
    }
#pragma unroll
    for (int o = 16; o; o >>= 1) {
        mnl = fminf(mnl, __shfl_xor_sync(0xffffffffu, mnl, o));
        mxl = fmaxf(mxl, __shfl_xor_sync(0xffffffffu, mxl, o));
        mnr = fminf(mnr, __shfl_xor_sync(0xffffffffu, mnr, o));
        mxr = fmaxf(mxr, __shfl_xor_sync(0xffffffffu, mxr, o));
    }
    __shared__ float s[8][4];
    int w = t >> 5, lane = t & 31;
    if (lane == 0) { s[w][0] = mnl; s[w][1] = mxl; s[w][2] = mnr; s[w][3] = mxr; }
    __syncthreads();
    if (t == 0) {
#pragma unroll
        for (int i = 1; i < 8; i++) {
            mnl = fminf(mnl, s[i][0]); mxl = fmaxf(mxl, s[i][1]);
            mnr = fminf(mnr, s[i][2]); mxr = fmaxf(mxr, s[i][3]);
        }
        float emin = mnl + mnr; emin = emin >= 0.f ? emin : 0.01f * emin;
        float emax = mxl + mxr; emax = emax >= 0.f ? emax : 0.01f * emax;
        float sc = 30.f / (emax - emin);
        sb[b * 2] = sc;
        sb[b * 2 + 1] = -emin * sc - 20.f;
    }
}

// ============================================================
// Tensor-core fused attention GEMM (warp mma.sync, split-bf16).
// SPLITOUT: write act(acc) as bf16 hi/lo (outh/outl);
// else write fp32 to outp. WFC2: also write att tile to fc2.
// ============================================================
template<int FH, bool ELU, bool WFC2, bool SPLITOUT>
__global__ __launch_bounds__(256) void att_mma_kernel(
    const float* __restrict__ el, const float* __restrict__ er,
    const float* __restrict__ sb,
    const bf16* __restrict__ hh, const bf16* __restrict__ hl,
    float* __restrict__ outp, bf16* __restrict__ outh, bf16* __restrict__ outl,
    float* __restrict__ fc2)
{
    __shared__ bf16 a_hi[128][40];
    __shared__ bf16 a_lo[128][40];
    __shared__ bf16 b_hi[32][136];
    __shared__ bf16 b_lo[32][136];

    const int t  = threadIdx.x;
    const int b  = blockIdx.z;
    const int i0 = blockIdx.x * 128;
    const int f0 = blockIdx.y * 128;
    const int w  = t >> 5, l = t & 31;
    const int wi0 = (w & 3) * 32;
    const int wf0 = (w >> 2) * 64;

    const float scale = sb[b * 2], bias = sb[b * 2 + 1];
    const float* erb = er + b * Nn;
    const int ai = t >> 1, aj = (t & 1) * 16;
    const float eli = el[b * Nn + i0 + ai];

    const int bj = t >> 3, bf = (t & 7) * 16;
    const bf16* hhb = hh + (size_t)b * Nn * FH + f0;
    const bf16* hlb = hl + (size_t)b * Nn * FH + f0;

    float acc[2][8][4];
#pragma unroll
    for (int m = 0; m < 2; m++)
#pragma unroll
        for (int n = 0; n < 8; n++)
#pragma unroll
            for (int q = 0; q < 4; q++) acc[m][n][q] = 0.f;

    const uint32_t aH = smem_u32(a_hi), aL = smem_u32(a_lo);
    const uint32_t bH = smem_u32(b_hi), bL = smem_u32(b_lo);
    const uint32_t lrow = (uint32_t)(l & 15), lhalf = (uint32_t)(l >> 4);

    for (int ch = 0; ch < Nn / 32; ch++) {
        const int j0 = ch * 32;
        float sv[16];
#pragma unroll
        for (int u = 0; u < 4; u++) {
            float4 e4 = *(const float4*)&erb[j0 + aj + u * 4];
            float xs[4] = {e4.x, e4.y, e4.z, e4.w};
#pragma unroll
            for (int q = 0; q < 4; q++) {
                float x = eli + xs[q];
                x = x >= 0.f ? x : 0.01f * x;
                x = scale * x + bias;
                sv[u * 4 + q] = 1.f / (1.f + __expf(-x));
            }
        }
        if (WFC2) {
            float* fr = fc2 + ((size_t)(b * Nn + i0 + ai)) * Nn + j0 + aj;
#pragma unroll
            for (int u = 0; u < 4; u++)
                *(float4*)&fr[u * 4] =
                    make_float4(sv[u*4], sv[u*4+1], sv[u*4+2], sv[u*4+3]);
        }
        {
            uint32_t hw[8], lw[8];
#pragma unroll
            for (int p = 0; p < 8; p++) {
                bf162 lo;
                bf162 hi = split_hi2(sv[p * 2], sv[p * 2 + 1], lo);
                hw[p] = *(uint32_t*)&hi;
                lw[p] = *(uint32_t*)&lo;
            }
            *(uint4*)&a_hi[ai][aj]     = make_uint4(hw[0], hw[1], hw[2], hw[3]);
            *(uint4*)&a_hi[ai][aj + 8] = make_uint4(hw[4], hw[5], hw[6], hw[7]);
            *(uint4*)&a_lo[ai][aj]     = make_uint4(lw[0], lw[1], lw[2], lw[3]);
            *(uint4*)&a_lo[ai][aj + 8] = make_uint4(lw[4], lw[5], lw[6], lw[7]);
        }
        {
            const bf16* sh = hhb + (size_t)(j0 + bj) * FH + bf;
            const bf16* sl = hlb + (size_t)(j0 + bj) * FH + bf;
            *(uint4*)&b_hi[bj][bf]     = *(const uint4*)sh;
            *(uint4*)&b_hi[bj][bf + 8] = *(const uint4*)(sh + 8);
            *(uint4*)&b_lo[bj][bf]     = *(const uint4*)sl;
            *(uint4*)&b_lo[bj][bf + 8] = *(const uint4*)(sl + 8);
        }
        __syncthreads();
#pragma unroll
        for (int ks = 0; ks < 2; ks++) {
            uint32_t ah[2][4], al2[2][4];
            uint32_t abase = (uint32_t)((wi0 + lrow) * 80 + ks * 32 + lhalf * 16);
            ldsm4(ah[0],  aH + abase);
            ldsm4(ah[1],  aH + abase + 16 * 80);
            ldsm4(al2[0], aL + abase);
            ldsm4(al2[1], aL + abase + 16 * 80);
#pragma unroll
            for (int nb2 = 0; nb2 < 4; nb2++) {
                uint32_t b4h[4], b4l[4];
                uint32_t ba = (uint32_t)((ks * 16 + lrow) * 272
                             + (wf0 + nb2 * 16) * 2 + lhalf * 16);
                ldsm4t(b4h, bH + ba);
                ldsm4t(b4l, bL + ba);
#pragma unroll
                for (int half = 0; half < 2; half++) {
                    int n = nb2 * 2 + half;
                    mma16816(acc[0][n], ah[0],  &b4h[half * 2]);
                    mma16816(acc[1][n], ah[1],  &b4h[half * 2]);
                    mma16816(acc[0][n], al2[0], &b4h[half * 2]);
                    mma16816(acc[1][n], al2[1], &b4h[half * 2]);
                    mma16816(acc[0][n], ah[0],  &b4l[half * 2]);
                    mma16816(acc[1][n], ah[1],  &b4l[half * 2]);
                }
            }
        }
        __syncthreads();
    }

    // epilogue
    const int r0 = l >> 2, c0 = (l & 3) * 2;
#pragma unroll
    for (int m = 0; m < 2; m++) {
        int row = i0 + wi0 + m * 16 + r0;
#pragma unroll
        for (int n = 0; n < 8; n++) {
            int col = f0 + wf0 + n * 8 + c0;
            float2 v0 = make_float2(acc[m][n][0], acc[m][n][1]);
            float2 v1 = make_float2(acc[m][n][2], acc[m][n][3]);
            if (ELU) {
                v0.x = v0.x > 0.f ? v0.x : __expf(v0.x) - 1.f;
                v0.y = v0.y > 0.f ? v0.y : __expf(v0.y) - 1.f;
                v1.x = v1.x > 0.f ? v1.x : __expf(v1.x) - 1.f;
                v1.y = v1.y > 0.f ? v1.y : __expf(v1.y) - 1.f;
            }
            if (SPLITOUT) {
                bf162 lo0, lo1;
                bf162 hi0 = split_hi2(v0.x, v0.y, lo0);
                bf162 hi1 = split_hi2(v1.x, v1.y, lo1);
                size_t base0 = (size_t)b * Nn * FH + (size_t)row * FH + col;
                size_t base1 = (size_t)b * Nn * FH + (size_t)(row + 8) * FH + col;
                *(bf162*)&outh[base0] = hi0;
                *(bf162*)&outl[base0] = lo0;
                *(bf162*)&outh[base1] = hi1;
                *(bf162*)&outl[base1] = lo1;
            } else {
                float* ob = outp + (size_t)b * Nn * FH;
                *(float2*)&ob[(size_t)row * FH + col]       = v0;
                *(float2*)&ob[(size_t)(row + 8) * FH + col] = v1;
            }
        }
    }
}

// ============================================================
// v[b,j] = g2[b,j,:] . Wg
// ============================================================
__global__ __launch_bounds__(256) void v_kernel(
    const float* __restrict__ g2, const float* __restrict__ Wg,
    float* __restrict__ v)
{
    int row = (blockIdx.x * blockDim.x + threadIdx.x) >> 5;
    int lane = threadIdx.x & 31;
    if (row >= Bn * Nn) return;
    const float* g = g2 + (size_t)row * H2n;
    float s = 0.f;
#pragma unroll
    for (int f = lane; f < H2n; f += 32) s += g[f] * Wg[f];
#pragma unroll
    for (int o = 16; o; o >>= 1) s += __shfl_xor_sync(0xffffffffu, s, o);
    if (lane == 0) v[row] = s;
}

// ============================================================
// out[b,i] = leaky( fc2[b,i,:] . v[b,:] + bg )
// ============================================================
__global__ __launch_bounds__(256) void z_kernel(
    const float* __restrict__ fc2, const float* __restrict__ v,
    const float* __restrict__ bg, float* __restrict__ out)
{
    int row = blockIdx.x;
    int b = row >> 10;
    int t = threadIdx.x;
    const float* fr = fc2 + (size_t)row * Nn;
    const float* vb = v + b * Nn;
    float4 f4 = *(const float4*)&fr[t * 4];
    float4 v4 = *(const float4*)&vb[t * 4];
    float s = f4.x * v4.x + f4.y * v4.y + f4.z * v4.z + f4.w * v4.w;
#pragma unroll
    for (int o = 16; o; o >>= 1) s += __shfl_xor_sync(0xffffffffu, s, o);
    __shared__ float red[8];
    int w = t >> 5, lane = t & 31;
    if (lane == 0) red[w] = s;
    __syncthreads();
    if (t == 0) {
        float z = red[0] + red[1] + red[2] + red[3]
                + red[4] + red[5] + red[6] + red[7] + bg[0];
        out[row] = z >= 0.f ? z : 0.01f * z;
    }
}

// ============================================================
extern "C" void kernel_launch(void* const* d_in, const int* in_sizes, int n_in,
                              void* d_out, int out_size)
{
    const float* x  = (const float*)d_in[0];
    // d_in[1] = edge_weight (unused by reference)
    const float* W1 = (const float*)d_in[2];
    const float* a1 = (const float*)d_in[3];
    const float* W2 = (const float*)d_in[4];
    const float* a2 = (const float*)d_in[5];
    const float* Wg = (const float*)d_in[6];
    const float* bg = (const float*)d_in[7];

    float* out = (float*)d_out;
    float* fc2 = out + (size_t)Bn * Nn;
    float* g2  = fc2 + (size_t)Bn * Nn * Nn;

    bf16 *xh, *xl, *w1h, *w1l, *w2h, *w2l, *h1h, *h1l, *g1h, *g1l, *h2h, *h2l;
    float *el, *er, *sb, *vv;
    cudaGetSymbolAddress((void**)&xh,  g_xh);
    cudaGetSymbolAddress((void**)&xl,  g_xl);
    cudaGetSymbolAddress((void**)&w1h, g_w1h);
    cudaGetSymbolAddress((void**)&w1l, g_w1l);
    cudaGetSymbolAddress((void**)&w2h, g_w2h);
    cudaGetSymbolAddress((void**)&w2l, g_w2l);
    cudaGetSymbolAddress((void**)&h1h, g_h1h);
    cudaGetSymbolAddress((void**)&h1l, g_h1l);
    cudaGetSymbolAddress((void**)&g1h, g_g1h);
    cudaGetSymbolAddress((void**)&g1l, g_g1l);
    cudaGetSymbolAddress((void**)&h2h, g_h2h);
    cudaGetSymbolAddress((void**)&h2l, g_h2l);
    cudaGetSymbolAddress((void**)&el,  g_el);
    cudaGetSymbolAddress((void**)&er,  g_er);
    cudaGetSymbolAddress((void**)&sb,  g_sb);
    cudaGetSymbolAddress((void**)&vv,  g_v);

    const int M = Bn * Nn;   // 32768

    // 0) splits of inputs
    split_kernel<<<(M * FIN / 4 + 255) / 256, 256>>>(x, xh, xl, M * FIN / 4);
    split_kernel<<<(FIN * H1n / 4 + 255) / 256, 256>>>(W1, w1h, w1l, FIN * H1n / 4);
    split_kernel<<<(H1n * H2n / 4 + 255) / 256, 256>>>(W2, w2h, w2l, H1n * H2n / 4);
    // 1) h1 = x @ W1  (split out)
    mma_gemm_kernel<FIN><<<dim3(H1n / 128, M / 128), 256>>>(
        xh, xl, w1h, w1l, h1h, h1l, H1n);
    // 2) el1/er1 + scale/bias
    eler_kernel<<<M / 8, 256>>>(h1h, h1l, a1, el, er, H1n);
    minmax_kernel<<<Bn, 256>>>(el, er, sb);
    // 3) g1 = elu(att1 @ h1)  (split out)
    att_mma_kernel<H1n, true, false, true>
        <<<dim3(Nn / 128, H1n / 128, Bn), 256>>>(el, er, sb, h1h, h1l,
                                                 nullptr, g1h, g1l, nullptr);
    // 4) h2 = g1 @ W2  (split out)
    mma_gemm_kernel<H1n><<<dim3(H2n / 128, M / 128), 256>>>(
        g1h, g1l, w2h, w2l, h2h, h2l, H2n);
    // 5) el2/er2 + scale/bias
    eler_kernel<<<M / 8, 256>>>(h2h, h2l, a2, el, er, H2n);
    minmax_kernel<<<Bn, 256>>>(el, er, sb);
    // 6) fc2 + g2 = att2 @ h2  (fp32 out)
    att_mma_kernel<H2n, false, true, false>
        <<<dim3(Nn / 128, 1, Bn), 256>>>(el, er, sb, h2h, h2l,
                                         g2, nullptr, nullptr, fc2);
    // 7) v = g2 @ Wg
    v_kernel<<<M / 8, 256>>>(g2, Wg, vv);
    // 8) out = leaky(fc2 @ v + bg)
    z_kernel<<<M, 256>>>(fc2, vv, bg, out);
}